// round 16
// baseline (speedup 1.0000x reference)
#include <cuda_runtime.h>
#include <cuda_fp16.h>
#include <cstdint>

// ---------------------------------------------------------------------------
// C[8192,4096] = A[8192,4096] * W[4096,4096]^T  (fp32 in/out)
// R15: fp16 m16n8k16 GEMM. vs R13 (best): the per-iteration __syncthreads is
// replaced by an mbarrier full/empty ring:
//   full[s] (count 128): cp.async.mbarrier.arrive + explicit arrive per thread
//   empty[s] (count 4): per-warp release right after the stage's LDSMs
// -> warps drift up to ~2 iterations instead of re-aligning every iteration.
// BM=128, BN=64, BK=64, 128 thr x 3 CTAs/SM, 3-stage XOR-swizzled ring.
// ---------------------------------------------------------------------------

#define MTOT 8192
#define KDIM 4096
#define NDIM 4096

#define BM 128
#define BN 64
#define BK 64
#define KITERS (KDIM / BK)        // 64
#define STAGES 3

// header: full[0..2] at 0,8,16 ; empty[0..2] at 24,32,40 ; data from 128
#define MB_FULL(s)  ((s) * 8)
#define MB_EMPTY(s) (24 + (s) * 8)
#define DATA0 128

// swizzled rows: 64 fp16 = 128B exactly; addr = row*128 + (k16off ^ (row&7)<<4)
#define ROWB 128
#define A_OFF DATA0
#define B_OFF (DATA0 + BM * ROWB)          // 128 + 16384
#define STAGE_BYTES ((BM + BN) * ROWB)     // 24576
#define SMEM_TOTAL (DATA0 + STAGES * STAGE_BYTES)  // 73856 (x3 CTAs ~222KB)

// fp16 scratch copies (device globals: allowed, no allocation)
__device__ __half g_Ah[(size_t)MTOT * KDIM];
__device__ __half g_Wh[(size_t)NDIM * KDIM];

// ------------------------------- helpers -----------------------------------

__device__ __forceinline__ uint32_t smem_u32(const void* p) {
    uint32_t a;
    asm("{ .reg .u64 t; cvta.to.shared.u64 t, %1; cvt.u32.u64 %0, t; }"
        : "=r"(a) : "l"(p));
    return a;
}

__device__ __forceinline__ void cp_async16(uint32_t dst, const void* src) {
    asm volatile("cp.async.cg.shared.global [%0], [%1], 16;\n"
                 :: "r"(dst), "l"(src) : "memory");
}

__device__ __forceinline__ void mbar_init(uint32_t addr, uint32_t cnt) {
    asm volatile("mbarrier.init.shared::cta.b64 [%0], %1;"
                 :: "r"(addr), "r"(cnt) : "memory");
}
__device__ __forceinline__ void mbar_arrive(uint32_t addr) {
    asm volatile("mbarrier.arrive.shared::cta.b64 _, [%0];"
                 :: "r"(addr) : "memory");
}
__device__ __forceinline__ void cp_async_mbar_arrive(uint32_t addr) {
    asm volatile("cp.async.mbarrier.arrive.shared::cta.b64 [%0];"
                 :: "r"(addr) : "memory");
}
__device__ __forceinline__ void mbar_wait(uint32_t addr, uint32_t parity) {
    asm volatile(
        "{\n\t"
        ".reg .pred P;\n\t"
        "WL_%=:\n\t"
        "mbarrier.try_wait.parity.shared::cta.b64 P, [%0], %1;\n\t"
        "@P bra.uni WD_%=;\n\t"
        "bra.uni WL_%=;\n\t"
        "WD_%=:\n\t"
        "}"
        :: "r"(addr), "r"(parity) : "memory");
}

__device__ __forceinline__ void ldsm_x4(uint32_t& r0, uint32_t& r1,
                                        uint32_t& r2, uint32_t& r3,
                                        uint32_t addr) {
    asm volatile("ldmatrix.sync.aligned.m8n8.x4.shared.b16 {%0,%1,%2,%3}, [%4];"
                 : "=r"(r0), "=r"(r1), "=r"(r2), "=r"(r3) : "r"(addr));
}

__device__ __forceinline__ void mma_f16(float* c, const uint32_t* a,
                                        const uint32_t* b) {
    asm volatile(
        "mma.sync.aligned.m16n8k16.row.col.f32.f16.f16.f32 "
        "{%0,%1,%2,%3}, {%4,%5,%6,%7}, {%8,%9}, {%0,%1,%2,%3};"
        : "+f"(c[0]), "+f"(c[1]), "+f"(c[2]), "+f"(c[3])
        : "r"(a[0]), "r"(a[1]), "r"(a[2]), "r"(a[3]),
          "r"(b[0]), "r"(b[1]));
}

// ------------------------------- prepass ------------------------------------

__global__ void __launch_bounds__(256) prepass_kernel(const float* __restrict__ A,
                                                      const float* __restrict__ W) {
    const long long nA = (long long)MTOT * KDIM / 4;
    const long long nW = (long long)NDIM * KDIM / 4;
    const long long stride = (long long)gridDim.x * blockDim.x;
    for (long long i = (long long)blockIdx.x * blockDim.x + threadIdx.x;
         i < nA + nW; i += stride) {
        const float4* src;
        __half* dst;
        long long j;
        if (i < nA) { src = (const float4*)A; dst = g_Ah; j = i; }
        else        { src = (const float4*)W; dst = g_Wh; j = i - nA; }
        float4 v = src[j];
        __half2* p = (__half2*)(dst + 4 * j);
        p[0] = __floats2half2_rn(v.x, v.y);
        p[1] = __floats2half2_rn(v.z, v.w);
    }
}

// ------------------------------- GEMM ---------------------------------------

__global__ void __launch_bounds__(128, 3) gemm_kernel(float* __restrict__ out) {
    extern __shared__ char smem[];
    const uint32_t sbase = smem_u32(smem);
    const int tid = threadIdx.x;
    const int lane = tid & 31;
    const int wid = tid >> 5;         // 0..3 -> 32-row strip (warp covers BN)
    const int grp = lane >> 2;
    const int tig = lane & 3;

    const int m_base = blockIdx.y * BM;
    const int n_base = blockIdx.x * BN;

    // --- mbarrier init ---
    if (tid == 0) {
        #pragma unroll
        for (int s = 0; s < STAGES; s++) {
            mbar_init(sbase + MB_FULL(s), 128);   // per-thread arrives
            mbar_init(sbase + MB_EMPTY(s), 4);    // per-warp arrives
        }
    }
    __syncthreads();   // one-time: barriers visible before any arrive

    // --- ldmatrix per-lane geometry (XOR swizzle) ---
    const int lj = lane >> 3;
    const int lr = lane & 7;
    const uint32_t xorv = (uint32_t)(lr << 4);
    const int arow = wid * 32 + (lj & 1) * 8 + lr;       // + t*16
    const uint32_t aBase = sbase + A_OFF + (uint32_t)(arow * ROWB);
    const uint32_t aK = (uint32_t)((lj >> 1) * 16);
    const int brow = (lj >> 1) * 8 + lr;                 // + p*16
    const uint32_t bBase = sbase + B_OFF + (uint32_t)(brow * ROWB);
    const uint32_t bK = (uint32_t)((lj & 1) * 16);

    // --- producer geometry ---
    const int prow = tid >> 3;        // 0..15
    const int pch = tid & 7;
    const uint32_t pxor = (uint32_t)(pch * 16);

    float acc[2][8][4];
    #pragma unroll
    for (int t = 0; t < 2; t++)
        #pragma unroll
        for (int j = 0; j < 8; j++)
            #pragma unroll
            for (int q = 0; q < 4; q++)
                acc[t][j][q] = 0.0f;

    auto produce = [&](int stage, int kb) {
        const uint32_t st = sbase + (uint32_t)(stage * STAGE_BYTES);
        const size_t kel = (size_t)kb * BK;
        #pragma unroll
        for (int j = 0; j < 8; j++) {          // A: 8 chunks/thread
            const int r = prow + 16 * j;
            const uint32_t sw = (uint32_t)(r * ROWB) + (pxor ^ ((uint32_t)(r & 7) << 4));
            cp_async16(st + A_OFF + sw,
                       g_Ah + (size_t)(m_base + r) * KDIM + kel + pch * 8);
        }
        #pragma unroll
        for (int j = 0; j < 4; j++) {          // B: 4 chunks/thread
            const int r = prow + 16 * j;
            const uint32_t sw = (uint32_t)(r * ROWB) + (pxor ^ ((uint32_t)(r & 7) << 4));
            cp_async16(st + B_OFF + sw,
                       g_Wh + (size_t)(n_base + r) * KDIM + kel + pch * 8);
        }
        // non-blocking completion signal: async arrive + explicit arrive
        cp_async_mbar_arrive(sbase + MB_FULL(stage));
        mbar_arrive(sbase + MB_FULL(stage));
    };

    // prologue: stages 0 and 1
    produce(0, 0);
    produce(1, 1);

    // fragment double buffers
    uint32_t af[2][2][4], bf[2][8][2];

    // ring counters
    int cs = 0, cph = 0, ccnt = 0;        // consumer stage / full parity
    int ps2 = 2;                          // producer stage (kb = it+2)
    int pph = 0, pcnt = 0;                // producer empty parity

    for (int it = 0; it < KITERS; ++it) {
        // ---- producer: stage for k-block it+2 ----
        if (it + 2 < KITERS) {
            if (it >= 1) {                // kb >= 3: stage previously used
                mbar_wait(sbase + MB_EMPTY(ps2), (uint32_t)pph);
                if (++pcnt == 3) { pcnt = 0; pph ^= 1; }
            }
            produce(ps2, it + 2);
            if (++ps2 == STAGES) ps2 = 0;
        }

        // ---- consumer: wait stage `it` data ----
        mbar_wait(sbase + MB_FULL(cs), (uint32_t)cph);
        if (++ccnt == 3) { ccnt = 0; cph ^= 1; }

        const uint32_t so = (uint32_t)(cs * STAGE_BYTES);

        // ks=0 fragments into buffer 0
        #pragma unroll
        for (int t = 0; t < 2; t++)
            ldsm_x4(af[0][t][0], af[0][t][1], af[0][t][2], af[0][t][3],
                    aBase + so + (uint32_t)(t * 16 * ROWB) + (aK ^ xorv));
        #pragma unroll
        for (int p = 0; p < 4; p++)
            ldsm_x4(bf[0][2 * p][0], bf[0][2 * p][1],
                    bf[0][2 * p + 1][0], bf[0][2 * p + 1][1],
                    bBase + so + (uint32_t)(p * 16 * ROWB) + (bK ^ xorv));

        #pragma unroll
        for (int ks = 0; ks < 4; ks++) {      // 4 x k16 = BK 64
            const int cur = ks & 1;
            const int nxt = cur ^ 1;
            if (ks < 3) {                      // prefetch ks+1 fragments
                const uint32_t ka = ((uint32_t)((ks + 1) * 32) + aK) ^ xorv;
                const uint32_t kb2 = ((uint32_t)((ks + 1) * 32) + bK) ^ xorv;
                #pragma unroll
                for (int t = 0; t < 2; t++)
                    ldsm_x4(af[nxt][t][0], af[nxt][t][1], af[nxt][t][2], af[nxt][t][3],
                            aBase + so + (uint32_t)(t * 16 * ROWB) + ka);
                #pragma unroll
                for (int p = 0; p < 4; p++)
                    ldsm_x4(bf[nxt][2 * p][0], bf[nxt][2 * p][1],
                            bf[nxt][2 * p + 1][0], bf[nxt][2 * p + 1][1],
                            bBase + so + (uint32_t)(p * 16 * ROWB) + kb2);
            }
            if (ks == 3) {
                // all LDSMs for this stage done -> release it (per-warp)
                __syncwarp();
                if (lane == 0) mbar_arrive(sbase + MB_EMPTY(cs));
            }
            #pragma unroll
            for (int t = 0; t < 2; t++)
                #pragma unroll
                for (int j = 0; j < 8; j++)
                    mma_f16(acc[t][j], af[cur][t], bf[cur][j]);
        }

        if (++cs == STAGES) cs = 0;
    }

    // epilogue: float2 stores (m16n8 C layout)
    #pragma unroll
    for (int t = 0; t < 2; t++) {
        const int r0 = m_base + wid * 32 + t * 16 + grp;
        #pragma unroll
        for (int j = 0; j < 8; j++) {
            const int cg = n_base + j * 8 + 2 * tig;
            float2 v0 = make_float2(acc[t][j][0], acc[t][j][1]);
            float2 v1 = make_float2(acc[t][j][2], acc[t][j][3]);
            *reinterpret_cast<float2*>(out + (size_t)r0 * NDIM + cg) = v0;
            *reinterpret_cast<float2*>(out + (size_t)(r0 + 8) * NDIM + cg) = v1;
        }
    }
}

// ------------------------------- launch --------------------------------------

extern "C" void kernel_launch(void* const* d_in, const int* in_sizes, int n_in,
                              void* d_out, int out_size) {
    const float* A = (const float*)d_in[0];   // [8,1024,4096] == [8192,4096]
    const float* W = (const float*)d_in[1];   // [4096,4096] (N,K)
    float* out = (float*)d_out;               // [8192,4096]
    (void)in_sizes; (void)n_in; (void)out_size;

    cudaFuncSetAttribute(gemm_kernel,
                         cudaFuncAttributeMaxDynamicSharedMemorySize, SMEM_TOTAL);

    prepass_kernel<<<1184, 256>>>(A, W);

    dim3 grid(NDIM / BN, MTOT / BM);   // (64, 64) = 4096 CTAs
    gemm_kernel<<<grid, 128, SMEM_TOTAL>>>(out);
}

// round 17
// speedup vs baseline: 1.0117x; 1.0117x over previous
#include <cuda_runtime.h>
#include <cuda_fp16.h>
#include <cstdint>

// ---------------------------------------------------------------------------
// C[8192,4096] = A[8192,4096] * W[4096,4096]^T  (fp32 in/out)
// R17: fp16 m16n8k16 GEMM. vs R15: 4 CTAs/SM (4 decoupled barrier domains,
// 4 warps/SMSP) enabled by a 2-stage mbarrier full/empty ring (no wait_group
// slack stages needed). Producer runs after the consume phase, gated on the
// empty barrier released right after each warp's LDSMs. Single-buffered
// fragments to fit the 128-reg cap. BM=128, BN=64, BK=64, 128 thr.
// ---------------------------------------------------------------------------

#define MTOT 8192
#define KDIM 4096
#define NDIM 4096

#define BM 128
#define BN 64
#define BK 64
#define KITERS (KDIM / BK)        // 64
#define STAGES 2

// header: full[0..1] at 0,8 ; empty[0..1] at 16,24 ; data from 128
#define MB_FULL(s)  ((s) * 8)
#define MB_EMPTY(s) (16 + (s) * 8)
#define DATA0 128

// swizzled rows: 64 fp16 = 128B exactly; addr = row*128 + (k16off ^ (row&7)<<4)
#define ROWB 128
#define A_OFF DATA0
#define B_OFF (DATA0 + BM * ROWB)
#define STAGE_BYTES ((BM + BN) * ROWB)     // 24576
#define SMEM_TOTAL (DATA0 + STAGES * STAGE_BYTES)  // 49280 (x4 CTAs = 197120/SM)

// fp16 scratch copies (device globals: allowed, no allocation)
__device__ __half g_Ah[(size_t)MTOT * KDIM];
__device__ __half g_Wh[(size_t)NDIM * KDIM];

// ------------------------------- helpers -----------------------------------

__device__ __forceinline__ uint32_t smem_u32(const void* p) {
    uint32_t a;
    asm("{ .reg .u64 t; cvta.to.shared.u64 t, %1; cvt.u32.u64 %0, t; }"
        : "=r"(a) : "l"(p));
    return a;
}

__device__ __forceinline__ void cp_async16(uint32_t dst, const void* src) {
    asm volatile("cp.async.cg.shared.global [%0], [%1], 16;\n"
                 :: "r"(dst), "l"(src) : "memory");
}

__device__ __forceinline__ void mbar_init(uint32_t addr, uint32_t cnt) {
    asm volatile("mbarrier.init.shared::cta.b64 [%0], %1;"
                 :: "r"(addr), "r"(cnt) : "memory");
}
__device__ __forceinline__ void mbar_arrive(uint32_t addr) {
    asm volatile("mbarrier.arrive.shared::cta.b64 _, [%0];"
                 :: "r"(addr) : "memory");
}
__device__ __forceinline__ void cp_async_mbar_arrive(uint32_t addr) {
    asm volatile("cp.async.mbarrier.arrive.shared::cta.b64 [%0];"
                 :: "r"(addr) : "memory");
}
__device__ __forceinline__ void mbar_wait(uint32_t addr, uint32_t parity) {
    asm volatile(
        "{\n\t"
        ".reg .pred P;\n\t"
        "WL_%=:\n\t"
        "mbarrier.try_wait.parity.shared::cta.b64 P, [%0], %1;\n\t"
        "@P bra.uni WD_%=;\n\t"
        "bra.uni WL_%=;\n\t"
        "WD_%=:\n\t"
        "}"
        :: "r"(addr), "r"(parity) : "memory");
}

__device__ __forceinline__ void ldsm_x4(uint32_t& r0, uint32_t& r1,
                                        uint32_t& r2, uint32_t& r3,
                                        uint32_t addr) {
    asm volatile("ldmatrix.sync.aligned.m8n8.x4.shared.b16 {%0,%1,%2,%3}, [%4];"
                 : "=r"(r0), "=r"(r1), "=r"(r2), "=r"(r3) : "r"(addr));
}

__device__ __forceinline__ void mma_f16(float* c, const uint32_t* a,
                                        const uint32_t* b) {
    asm volatile(
        "mma.sync.aligned.m16n8k16.row.col.f32.f16.f16.f32 "
        "{%0,%1,%2,%3}, {%4,%5,%6,%7}, {%8,%9}, {%0,%1,%2,%3};"
        : "+f"(c[0]), "+f"(c[1]), "+f"(c[2]), "+f"(c[3])
        : "r"(a[0]), "r"(a[1]), "r"(a[2]), "r"(a[3]),
          "r"(b[0]), "r"(b[1]));
}

// ------------------------------- prepass ------------------------------------

__global__ void __launch_bounds__(256) prepass_kernel(const float* __restrict__ A,
                                                      const float* __restrict__ W) {
    const long long nA = (long long)MTOT * KDIM / 4;
    const long long nW = (long long)NDIM * KDIM / 4;
    const long long stride = (long long)gridDim.x * blockDim.x;
    for (long long i = (long long)blockIdx.x * blockDim.x + threadIdx.x;
         i < nA + nW; i += stride) {
        const float4* src;
        __half* dst;
        long long j;
        if (i < nA) { src = (const float4*)A; dst = g_Ah; j = i; }
        else        { src = (const float4*)W; dst = g_Wh; j = i - nA; }
        float4 v = src[j];
        __half2* p = (__half2*)(dst + 4 * j);
        p[0] = __floats2half2_rn(v.x, v.y);
        p[1] = __floats2half2_rn(v.z, v.w);
    }
}

// ------------------------------- GEMM ---------------------------------------

__global__ void __launch_bounds__(128, 4) gemm_kernel(float* __restrict__ out) {
    extern __shared__ char smem[];
    const uint32_t sbase = smem_u32(smem);
    const int tid = threadIdx.x;
    const int lane = tid & 31;
    const int wid = tid >> 5;         // 0..3 -> 32-row strip (warp covers BN)
    const int grp = lane >> 2;
    const int tig = lane & 3;

    const int m_base = blockIdx.y * BM;
    const int n_base = blockIdx.x * BN;

    // --- mbarrier init ---
    if (tid == 0) {
        #pragma unroll
        for (int s = 0; s < STAGES; s++) {
            mbar_init(sbase + MB_FULL(s), 128);   // explicit per-thread arrives
            mbar_init(sbase + MB_EMPTY(s), 4);    // per-warp releases
        }
    }
    __syncthreads();   // one-time: barriers visible before any arrive

    // --- ldmatrix per-lane geometry (XOR swizzle) ---
    const int lj = lane >> 3;
    const int lr = lane & 7;
    const uint32_t xorv = (uint32_t)(lr << 4);
    const int arow = wid * 32 + (lj & 1) * 8 + lr;       // + t*16
    const uint32_t aBase = sbase + A_OFF + (uint32_t)(arow * ROWB);
    const uint32_t aK = (uint32_t)((lj >> 1) * 16);
    const int brow = (lj >> 1) * 8 + lr;                 // + p*16
    const uint32_t bBase = sbase + B_OFF + (uint32_t)(brow * ROWB);
    const uint32_t bK = (uint32_t)((lj & 1) * 16);

    // --- producer geometry ---
    const int prow = tid >> 3;        // 0..15
    const int pch = tid & 7;
    const uint32_t pxor = (uint32_t)(pch * 16);

    float acc[2][8][4];
    #pragma unroll
    for (int t = 0; t < 2; t++)
        #pragma unroll
        for (int j = 0; j < 8; j++)
            #pragma unroll
            for (int q = 0; q < 4; q++)
                acc[t][j][q] = 0.0f;

    auto produce = [&](int stage, int kb) {
        const uint32_t st = sbase + (uint32_t)(stage * STAGE_BYTES);
        const size_t kel = (size_t)kb * BK;
        #pragma unroll
        for (int j = 0; j < 8; j++) {          // A: 8 chunks/thread
            const int r = prow + 16 * j;
            const uint32_t sw = (uint32_t)(r * ROWB) + (pxor ^ ((uint32_t)(r & 7) << 4));
            cp_async16(st + A_OFF + sw,
                       g_Ah + (size_t)(m_base + r) * KDIM + kel + pch * 8);
        }
        #pragma unroll
        for (int j = 0; j < 4; j++) {          // B: 4 chunks/thread
            const int r = prow + 16 * j;
            const uint32_t sw = (uint32_t)(r * ROWB) + (pxor ^ ((uint32_t)(r & 7) << 4));
            cp_async16(st + B_OFF + sw,
                       g_Wh + (size_t)(n_base + r) * KDIM + kel + pch * 8);
        }
        // count-neutral async arrive (incs pending at issue, arrives at
        // completion) + explicit arrive -> phase flips only when data landed
        cp_async_mbar_arrive(sbase + MB_FULL(stage));
        mbar_arrive(sbase + MB_FULL(stage));
    };

    // prologue: fill both stages
    produce(0, 0);
    produce(1, 1);

    for (int it = 0; it < KITERS; ++it) {
        const int cs = it & 1;
        const uint32_t par = (uint32_t)((it >> 1) & 1);   // full AND empty parity

        // ---- consume stage `cs` (k-block it) ----
        mbar_wait(sbase + MB_FULL(cs), par);
        const uint32_t so = (uint32_t)(cs * STAGE_BYTES);

        uint32_t a[2][4], b[8][2];
        #pragma unroll
        for (int ks = 0; ks < 4; ks++) {      // 4 x k16 = BK 64
            const uint32_t ka = ((uint32_t)(ks * 32) + aK) ^ xorv;
            const uint32_t kb2 = ((uint32_t)(ks * 32) + bK) ^ xorv;
            #pragma unroll
            for (int t = 0; t < 2; t++)
                ldsm_x4(a[t][0], a[t][1], a[t][2], a[t][3],
                        aBase + so + (uint32_t)(t * 16 * ROWB) + ka);
            #pragma unroll
            for (int p = 0; p < 4; p++)
                ldsm_x4(b[2 * p][0], b[2 * p][1], b[2 * p + 1][0], b[2 * p + 1][1],
                        bBase + so + (uint32_t)(p * 16 * ROWB) + kb2);
            if (ks == 3) {
                // this warp's LDSMs for the stage are done -> release it
                __syncwarp();
                if (lane == 0) mbar_arrive(sbase + MB_EMPTY(cs));
            }
            #pragma unroll
            for (int t = 0; t < 2; t++)
                #pragma unroll
                for (int j = 0; j < 8; j++)
                    mma_f16(acc[t][j], a[t], b[j]);
        }

        // ---- refill stage `cs` with k-block it+2 ----
        if (it + 2 < KITERS) {
            mbar_wait(sbase + MB_EMPTY(cs), par);   // all 4 warps released
            produce(cs, it + 2);
        }
    }

    // epilogue: float2 stores (m16n8 C layout)
    #pragma unroll
    for (int t = 0; t < 2; t++) {
        const int r0 = m_base + wid * 32 + t * 16 + grp;
        #pragma unroll
        for (int j = 0; j < 8; j++) {
            const int cg = n_base + j * 8 + 2 * tig;
            float2 v0 = make_float2(acc[t][j][0], acc[t][j][1]);
            float2 v1 = make_float2(acc[t][j][2], acc[t][j][3]);
            *reinterpret_cast<float2*>(out + (size_t)r0 * NDIM + cg) = v0;
            *reinterpret_cast<float2*>(out + (size_t)(r0 + 8) * NDIM + cg) = v1;
        }
    }
}

// ------------------------------- launch --------------------------------------

extern "C" void kernel_launch(void* const* d_in, const int* in_sizes, int n_in,
                              void* d_out, int out_size) {
    const float* A = (const float*)d_in[0];   // [8,1024,4096] == [8192,4096]
    const float* W = (const float*)d_in[1];   // [4096,4096] (N,K)
    float* out = (float*)d_out;               // [8192,4096]
    (void)in_sizes; (void)n_in; (void)out_size;

    cudaFuncSetAttribute(gemm_kernel,
                         cudaFuncAttributeMaxDynamicSharedMemorySize, SMEM_TOTAL);

    prepass_kernel<<<1184, 256>>>(A, W);

    dim3 grid(NDIM / BN, MTOT / BM);   // (64, 64) = 4096 CTAs
    gemm_kernel<<<grid, 128, SMEM_TOTAL>>>(out);
}